// round 16
// baseline (speedup 1.0000x reference)
#include <cuda_runtime.h>

// out = noised + 0.1f * noise   (elementwise, fp32)
// N = 64*3*512*512 = 50,331,648 -> n4 = 12,582,912 float4 (divisible by 1024).
//
// Measured landscape (bench = scoring metric; gap = bench - ncu kernel):
//   float4 256thr/49152blk (R4/R10): kernel 81.5-82.3, bench 88.8-88.9, gap ~7
//   float4 512thr/24576blk (R11):    kernel 84.3,      bench 88.45,     gap 4.1  <- best
//   float4 1024thr/12288blk (R12):   kernel 86.7,      bench 89.5,      gap 2.75
//   v8 variants:                     bench 90.2-90.5 (gap 9-11)
// Gap scales ~0.145ns/CTA (graph-replay dispatch overhead). 1024-thr blocks
// hurt occupancy/DRAM more than the gap saved. R13: decouple — block=512 with
// 2 float4 per thread (block-coalesced) -> 12,288 CTAs (R12's dispatch cost)
// at 512-thr occupancy (R11's DRAM behavior). Predict bench 87.5-88.3.

__global__ void __launch_bounds__(512)
gaussian_noise_add_kernel(const float4* __restrict__ noised,
                          const float4* __restrict__ noise,
                          float4* __restrict__ out,
                          int n4)
{
    int i0 = blockIdx.x * 1024 + threadIdx.x;
    int i1 = i0 + 512;

    if (i1 < n4) {
        float4 a0 = noised[i0];
        float4 a1 = noised[i1];
        float4 b0 = noise[i0];
        float4 b1 = noise[i1];
        float4 r0, r1;
        r0.x = fmaf(0.1f, b0.x, a0.x);
        r0.y = fmaf(0.1f, b0.y, a0.y);
        r0.z = fmaf(0.1f, b0.z, a0.z);
        r0.w = fmaf(0.1f, b0.w, a0.w);
        r1.x = fmaf(0.1f, b1.x, a1.x);
        r1.y = fmaf(0.1f, b1.y, a1.y);
        r1.z = fmaf(0.1f, b1.z, a1.z);
        r1.w = fmaf(0.1f, b1.w, a1.w);
        out[i0] = r0;
        out[i1] = r1;
    } else {
        // Remainder path (not taken for this shape: n4 % 1024 == 0).
        if (i0 < n4) {
            float4 a = noised[i0];
            float4 b = noise[i0];
            float4 r;
            r.x = fmaf(0.1f, b.x, a.x);
            r.y = fmaf(0.1f, b.y, a.y);
            r.z = fmaf(0.1f, b.z, a.z);
            r.w = fmaf(0.1f, b.w, a.w);
            out[i0] = r;
        }
    }
}

// Scalar tail kernel (defensive; n divisible by 4 here so never launched).
__global__ void gaussian_noise_tail_kernel(const float* __restrict__ noised,
                                           const float* __restrict__ noise,
                                           float* __restrict__ out,
                                           int start, int n)
{
    int i = start + blockIdx.x * blockDim.x + threadIdx.x;
    if (i < n) {
        out[i] = fmaf(0.1f, noise[i], noised[i]);
    }
}

extern "C" void kernel_launch(void* const* d_in, const int* in_sizes, int n_in,
                              void* d_out, int out_size)
{
    const float* noised = (const float*)d_in[0];
    const float* noise  = (const float*)d_in[1];
    float* out = (float*)d_out;
    int n = in_sizes[0];

    int n4 = n >> 2;
    if (n4 > 0) {
        const int threads = 512;
        const int per_block = 1024;  // 2 float4 per thread
        int blocks = (n4 + per_block - 1) / per_block;
        gaussian_noise_add_kernel<<<blocks, threads>>>(
            (const float4*)noised, (const float4*)noise, (float4*)out, n4);
    }
    int rem = n - (n4 << 2);
    if (rem > 0) {
        gaussian_noise_tail_kernel<<<1, 256>>>(noised, noise, out, n4 << 2, n);
    }
}

// round 17
// speedup vs baseline: 1.0159x; 1.0159x over previous
#include <cuda_runtime.h>

// out = noised + 0.1f * noise   (elementwise, fp32)
// N = 64*3*512*512 = 50,331,648 -> n4 = 12,582,912 float4 (divisible by 384? no
// — guarded). Traffic floor 604 MB/pass.
//
// Measured landscape (bench = scoring metric; gap = bench - ncu kernel):
//   float4 VPT1 256thr/49152 (R4/R10): kernel 81.5-82.3, bench 88.8-88.9, gap ~7
//   float4 VPT1 512thr/24576 (R11):    kernel 84.3, bench 88.45, gap 4.1  <- best
//   float4 VPT1 1024thr/12288 (R12):   kernel 86.7, bench 89.5,  gap 2.75
//   float4 VPT2 512thr/12288 (R13):    kernel 80.6, bench 89.9,  gap 9.3
//   v8 family:                         bench 90.2-90.5, gap 9-11
// Within the float4-VPT1 family gap falls with CTA count; any per-thread load
// batching (VPT>=2 / v8) inflates the gap ~3-5us. All configs land 88.4-90.5:
// grazing the steady-state 2R:1W DRAM ceiling. R14: probe the untested
// within-family point 384thr/32768CTA (5 CTAs/SM = 93.75% theoretical occ).

__global__ void __launch_bounds__(384)
gaussian_noise_add_kernel(const float4* __restrict__ noised,
                          const float4* __restrict__ noise,
                          float4* __restrict__ out,
                          int n4)
{
    int i = blockIdx.x * blockDim.x + threadIdx.x;
    if (i < n4) {
        float4 a = noised[i];
        float4 b = noise[i];
        float4 r;
        r.x = fmaf(0.1f, b.x, a.x);
        r.y = fmaf(0.1f, b.y, a.y);
        r.z = fmaf(0.1f, b.z, a.z);
        r.w = fmaf(0.1f, b.w, a.w);
        out[i] = r;
    }
}

// Scalar tail kernel (defensive; n divisible by 4 here so never launched).
__global__ void gaussian_noise_tail_kernel(const float* __restrict__ noised,
                                           const float* __restrict__ noise,
                                           float* __restrict__ out,
                                           int start, int n)
{
    int i = start + blockIdx.x * blockDim.x + threadIdx.x;
    if (i < n) {
        out[i] = fmaf(0.1f, noise[i], noised[i]);
    }
}

extern "C" void kernel_launch(void* const* d_in, const int* in_sizes, int n_in,
                              void* d_out, int out_size)
{
    const float* noised = (const float*)d_in[0];
    const float* noise  = (const float*)d_in[1];
    float* out = (float*)d_out;
    int n = in_sizes[0];

    int n4 = n >> 2;
    if (n4 > 0) {
        int threads = 384;
        int blocks = (n4 + threads - 1) / threads;
        gaussian_noise_add_kernel<<<blocks, threads>>>(
            (const float4*)noised, (const float4*)noise, (float4*)out, n4);
    }
    int rem = n - (n4 << 2);
    if (rem > 0) {
        gaussian_noise_tail_kernel<<<1, 256>>>(noised, noise, out, n4 << 2, n);
    }
}